// round 6
// baseline (speedup 1.0000x reference)
#include <cuda_runtime.h>
#include <cuda_fp16.h>
#include <math.h>
#include <stdint.h>

#define NB 4
#define NS 2048
#define ND 1024
#define NH 8
#define NK 128
#define NL 4
#define NM (NB*NS)

// ---------------- scratch ----------------------------------------------------
__device__ float  g_x  [NM*ND];
__device__ float  g_t1 [NM*ND];
__device__ __half g_x16[NM*ND];
__device__ __half g_q  [NM*ND];
__device__ __half g_k  [NM*ND];
__device__ __half g_v  [NM*ND];
__device__ __half g_ao [NM*ND];
__device__ __half g_h  [NM*ND];
__device__ __half g_wtd[12*ND*ND];      // dense weights transposed [l][3][N][K] f16
__device__ __half g_wtq[12*ND*ND];      // qkv weights  transposed [l][3][H*128][K] f16
__device__ __half g_mb [(size_t)NB*NS*NS]; // mask bias: 0 or -30000 (f16)

// ---------------- helpers ----------------------------------------------------
__device__ __forceinline__ float gelu_exact(float x) {
    return 0.5f * x * (1.0f + erff(x * 0.7071067811865476f));
}
__device__ __forceinline__ unsigned sptr(const void* p) {
    return (unsigned)__cvta_generic_to_shared(p);
}
__device__ __forceinline__ unsigned h2pack(float x, float y) {
    __half2 h = __floats2half2_rn(x, y);
    return *(unsigned*)&h;
}
__device__ __forceinline__ void ldsm4(unsigned r[4], unsigned a) {
    asm volatile("ldmatrix.sync.aligned.m8n8.x4.shared.b16 {%0,%1,%2,%3}, [%4];\n"
        : "=r"(r[0]), "=r"(r[1]), "=r"(r[2]), "=r"(r[3]) : "r"(a));
}
__device__ __forceinline__ void ldsm4t(unsigned r[4], unsigned a) {
    asm volatile("ldmatrix.sync.aligned.m8n8.x4.trans.shared.b16 {%0,%1,%2,%3}, [%4];\n"
        : "=r"(r[0]), "=r"(r[1]), "=r"(r[2]), "=r"(r[3]) : "r"(a));
}
__device__ __forceinline__ void mma16816(float c[4], const unsigned a[4],
                                         unsigned b0, unsigned b1) {
    asm volatile("mma.sync.aligned.m16n8k16.row.col.f32.f16.f16.f32 "
        "{%0,%1,%2,%3}, {%4,%5,%6,%7}, {%8,%9}, {%0,%1,%2,%3};\n"
        : "+f"(c[0]), "+f"(c[1]), "+f"(c[2]), "+f"(c[3])
        : "r"(a[0]), "r"(a[1]), "r"(a[2]), "r"(a[3]), "r"(b0), "r"(b1));
}
#define CP16(dst, src) \
    asm volatile("cp.async.cg.shared.global [%0], [%1], 16;" :: "r"(dst), "l"(src) : "memory")
#define CP_COMMIT() asm volatile("cp.async.commit_group;" ::: "memory")

__global__ void copy_in(const float4* __restrict__ s, float4* __restrict__ dx,
                        uint2* __restrict__ dh) {
    int i = blockIdx.x * blockDim.x + threadIdx.x;
    float4 v = s[i];
    dx[i] = v;
    uint2 hh; hh.x = h2pack(v.x, v.y); hh.y = h2pack(v.z, v.w);
    dh[i] = hh;
}

// mask int32 -> f16 additive bias (am==0 -> -30000, else 0)
__global__ void prep_mask(const int4* __restrict__ m, uint2* __restrict__ o) {
    size_t i = (size_t)blockIdx.x * blockDim.x + threadIdx.x;
    int4 v = ((const int4*)m)[i];
    uint2 r;
    r.x = h2pack(v.x == 0 ? -30000.f : 0.f, v.y == 0 ? -30000.f : 0.f);
    r.y = h2pack(v.z == 0 ? -30000.f : 0.f, v.w == 0 ? -30000.f : 0.f);
    o[i] = r;
}

// ---------------- weight transposes (f32 [K][N] -> f16 [N][K]) --------------
__global__ void tr_dense(const float* __restrict__ wo, const float* __restrict__ w1,
                         const float* __restrict__ w2, __half* __restrict__ dst) {
    __shared__ float tile[32][33];
    int z = blockIdx.z, l = z / 3, which = z % 3;
    const float* W = (which == 0 ? wo : which == 1 ? w1 : w2) + (size_t)l * ND * ND;
    __half* D = dst + (size_t)z * ND * ND;
    int n0 = blockIdx.x * 32, k0 = blockIdx.y * 32;
    int tx = threadIdx.x, ty = threadIdx.y;
#pragma unroll
    for (int i = 0; i < 32; i += 8)
        tile[ty + i][tx] = W[(size_t)(k0 + ty + i) * ND + n0 + tx];
    __syncthreads();
#pragma unroll
    for (int i = 0; i < 32; i += 8)
        D[(size_t)(n0 + ty + i) * ND + k0 + tx] = __float2half_rn(tile[tx][ty + i]);
}

__global__ void tr_qkv(const float* __restrict__ wq, const float* __restrict__ wk,
                       const float* __restrict__ wv, __half* __restrict__ dst) {
    __shared__ float tile[32][33];
    int z = blockIdx.z;                 // (l*3+sel)*8 + h
    int l = z / 24, rem = z % 24, sel = rem / 8, h = rem % 8;
    const float* W = (sel == 0 ? wq : sel == 1 ? wk : wv) + (size_t)(l * NH + h) * ND * NK;
    __half* D = dst + (size_t)((l * 3 + sel) * 8 + h) * NK * ND;
    int n0 = blockIdx.x * 32, k0 = blockIdx.y * 32;
    int tx = threadIdx.x, ty = threadIdx.y;
#pragma unroll
    for (int i = 0; i < 32; i += 8)
        tile[ty + i][tx] = W[(size_t)(k0 + ty + i) * NK + n0 + tx];
    __syncthreads();
#pragma unroll
    for (int i = 0; i < 32; i += 8)
        D[(size_t)(n0 + ty + i) * ND + k0 + tx] = __float2half_rn(tile[tx][ty + i]);
}

// ============================================================================
// GEMM v3: block 256x128, 256 threads (8 warps), warp 64x64, K-chunk 32,
// cp.async double-buffer, XOR-swizzled 64B rows.
// mode: 0 = f32 out, 1 = half+gelu, 2 = qkv scatter (gridDim.z=3 selects W/b/out)
// ============================================================================
#define BK 32
#define V3_ASZ (256*BK)
#define V3_BSZ (128*BK)
#define GEMM_SMEM_BYTES (2*(V3_ASZ+V3_BSZ)*2)   // 48 KB

__global__ __launch_bounds__(256) void gemm_v3(
    const __half* __restrict__ A, const __half* __restrict__ BtBase,
    const float* __restrict__ bias0, const float* __restrict__ bias1,
    const float* __restrict__ bias2,
    float* __restrict__ Cf, __half* __restrict__ Ch0,
    __half* __restrict__ Ch1, __half* __restrict__ Ch2, int mode)
{
    extern __shared__ __half smh[];
    __half* sA = smh;                       // [2][256][32] swizzled
    __half* sB = smh + 2 * V3_ASZ;          // [2][128][32]

    const int tid = threadIdx.x, lane = tid & 31, wid = tid >> 5;
    const int wm = wid >> 1, wn = wid & 1, g = lane >> 2, t = lane & 3;
    const int m0 = blockIdx.y * 256, n0 = blockIdx.x * 128;

    const int sel = blockIdx.z;
    const __half* Bt = BtBase + (size_t)sel * ND * ND;
    const float* bias = (sel == 0) ? bias0 : (sel == 1) ? bias1 : bias2;
    __half* Ch = (sel == 0) ? Ch0 : (sel == 1) ? Ch1 : Ch2;

    float c[4][8][4];
#pragma unroll
    for (int mt = 0; mt < 4; mt++)
#pragma unroll
        for (int nt = 0; nt < 8; nt++)
#pragma unroll
            for (int i = 0; i < 4; i++) c[mt][nt][i] = 0.f;

    const int lr = tid >> 2;                // 0..63
    const int lu = tid & 3;
    const unsigned sA0 = sptr(sA), sB0 = sptr(sB);

    const int arow = wm * 64 + (lane & 15);
    const int axor = (arow >> 1) & 3;
    const int ahi  = lane >> 4;
    const int brow = (lane >> 4) * 8 + (lane & 7);
    const int bxor = (brow >> 1) & 3;
    const int bhi  = (lane >> 3) & 1;

#define LOAD_CHUNK(ck, buf) do {                                              \
    int _k0 = (ck) * BK;                                                      \
    _Pragma("unroll")                                                         \
    for (int _i = 0; _i < 4; _i++) {                                          \
        int _r = lr + _i * 64;                                                \
        unsigned _sw = ((unsigned)(lu ^ ((_r >> 1) & 3))) * 16;               \
        CP16(sA0 + (buf) * V3_ASZ * 2 + _r * 64 + _sw,                        \
             A + (size_t)(m0 + _r) * ND + _k0 + lu * 8);                      \
    }                                                                         \
    _Pragma("unroll")                                                         \
    for (int _i = 0; _i < 2; _i++) {                                          \
        int _r = lr + _i * 64;                                                \
        unsigned _sw = ((unsigned)(lu ^ ((_r >> 1) & 3))) * 16;               \
        CP16(sB0 + (buf) * V3_BSZ * 2 + _r * 64 + _sw,                        \
             Bt + (size_t)(n0 + _r) * ND + _k0 + lu * 8);                     \
    }                                                                         \
    CP_COMMIT();                                                              \
} while (0)

    LOAD_CHUNK(0, 0);

    for (int ck = 0; ck < ND / BK; ck++) {
        int buf = ck & 1;
        if (ck + 1 < ND / BK) {
            LOAD_CHUNK(ck + 1, buf ^ 1);
            asm volatile("cp.async.wait_group 1;" ::: "memory");
        } else {
            asm volatile("cp.async.wait_group 0;" ::: "memory");
        }
        __syncthreads();

        unsigned abuf = sA0 + buf * V3_ASZ * 2;
        unsigned bbuf = sB0 + buf * V3_BSZ * 2;
#pragma unroll
        for (int ks = 0; ks < 2; ks++) {
            unsigned akoff = ((unsigned)((ks * 2 + ahi) ^ axor)) * 16;
            unsigned a[4][4];
#pragma unroll
            for (int mt = 0; mt < 4; mt++)
                ldsm4(a[mt], abuf + (arow + mt * 16) * 64 + akoff);
            unsigned bkoff = ((unsigned)((ks * 2 + bhi) ^ bxor)) * 16;
#pragma unroll
            for (int p = 0; p < 4; p++) {
                unsigned bf[4];
                ldsm4(bf, bbuf + (brow + wn * 64 + p * 16) * 64 + bkoff);
#pragma unroll
                for (int mt = 0; mt < 4; mt++) {
                    mma16816(c[mt][2 * p],     a[mt], bf[0], bf[1]);
                    mma16816(c[mt][2 * p + 1], a[mt], bf[2], bf[3]);
                }
            }
        }
        __syncthreads();
    }

    // epilogue
#pragma unroll
    for (int mt = 0; mt < 4; mt++) {
        int r0 = m0 + wm * 64 + mt * 16 + g;
#pragma unroll
        for (int nt = 0; nt < 8; nt++) {
            int col = n0 + wn * 64 + nt * 8 + 2 * t;
            float b0 = bias[col], b1 = bias[col + 1];
            float v0 = c[mt][nt][0] + b0, v1 = c[mt][nt][1] + b1;
            float v2 = c[mt][nt][2] + b0, v3 = c[mt][nt][3] + b1;
            if (mode == 0) {
                *(float2*)(Cf + (size_t)r0 * ND + col)       = make_float2(v0, v1);
                *(float2*)(Cf + (size_t)(r0 + 8) * ND + col) = make_float2(v2, v3);
            } else if (mode == 1) {
                v0 = gelu_exact(v0); v1 = gelu_exact(v1);
                v2 = gelu_exact(v2); v3 = gelu_exact(v3);
                *(unsigned*)(Ch + (size_t)r0 * ND + col)       = h2pack(v0, v1);
                *(unsigned*)(Ch + (size_t)(r0 + 8) * ND + col) = h2pack(v2, v3);
            } else {
                int head = col >> 7, within = col & 127;
                int bb0 = r0 >> 11, s0 = r0 & (NS - 1);
                __half* d0 = Ch + ((size_t)(bb0 * NH + head) * NS + s0) * NK + within;
                *(unsigned*)(d0)          = h2pack(v0, v1);
                *(unsigned*)(d0 + 8 * NK) = h2pack(v2, v3);
            }
        }
    }
}

// ============================================================================
// Flash attention fp16, f16 additive mask bias. BQ=128, BT=64, 256 threads.
// ============================================================================
#define QS_STR 136
#define KS_STR 136
#define VS_STR 136
#define PS_STR 72
#define OFF_Q 0
#define OFF_K (128*QS_STR)
#define OFF_V (OFF_K + 64*KS_STR)
#define OFF_P (OFF_V + 64*VS_STR)
#define HALF_END (OFF_P + 128*PS_STR)
#define SOFF_M    0
#define SOFF_L    128
#define SOFF_RMAX 256
#define SOFF_RSUM 512
#define ATTN_SMEM_BYTES (HALF_END*2 + 768*4)

__global__ __launch_bounds__(256) void attn_f16(
    const __half* __restrict__ Qg, const __half* __restrict__ Kg,
    const __half* __restrict__ Vg, const __half* __restrict__ Bg,
    __half* __restrict__ Og)
{
    extern __shared__ __half smh[];
    float* smf = (float*)((char*)smh + HALF_END * 2);

    const int tid = threadIdx.x, lane = tid & 31, w = tid >> 5;
    const int wm = w >> 1, wn = w & 1, g = lane >> 2, t = lane & 3;
    const int bh = blockIdx.y, b = bh >> 3, h = bh & 7;
    const int q0 = blockIdx.x * 128;

    const __half* Qb = Qg + ((size_t)bh * NS + q0) * NK;
#pragma unroll
    for (int i = 0; i < 8; i++) {
        int idx = tid + i * 256;
        int r = idx >> 4, c8 = (idx & 15) * 8;
        *(uint4*)&smh[OFF_Q + r * QS_STR + c8] = *(const uint4*)(Qb + (size_t)r * NK + c8);
    }
    if (tid < 128) { smf[SOFF_M + tid] = -INFINITY; smf[SOFF_L + tid] = 0.f; }

    float accz[2][8][4];
#pragma unroll
    for (int mt = 0; mt < 2; mt++)
#pragma unroll
        for (int nt = 0; nt < 8; nt++)
#pragma unroll
            for (int i = 0; i < 4; i++) accz[mt][nt][i] = 0.f;

    const float scale = 0.08838834764831845f;

    for (int t0 = 0; t0 < NS; t0 += 64) {
        __syncthreads();
        const __half* Kb = Kg + ((size_t)bh * NS + t0) * NK;
        const __half* Vb = Vg + ((size_t)bh * NS + t0) * NK;
#pragma unroll
        for (int i = 0; i < 4; i++) {
            int idx = tid + i * 256;
            int r = idx >> 4, c8 = (idx & 15) * 8;
            *(uint4*)&smh[OFF_K + r * KS_STR + c8] = *(const uint4*)(Kb + (size_t)r * NK + c8);
            *(uint4*)&smh[OFF_V + r * VS_STR + c8] = *(const uint4*)(Vb + (size_t)r * NK + c8);
        }
        __syncthreads();

        float sc[2][4][4];
#pragma unroll
        for (int mt = 0; mt < 2; mt++)
#pragma unroll
            for (int nt = 0; nt < 4; nt++)
#pragma unroll
                for (int i = 0; i < 4; i++) sc[mt][nt][i] = 0.f;

        {
            unsigned qbase = sptr(smh + OFF_Q) +
                ((wm * 32 + (lane & 15)) * QS_STR + (lane >> 4) * 8) * 2;
            unsigned kbase = sptr(smh + OFF_K) +
                (((lane >> 4) * 8 + (lane & 7)) * KS_STR + ((lane >> 3) & 1) * 8) * 2;
#pragma unroll
            for (int ks = 0; ks < 8; ks++) {
                unsigned a0[4], a1[4];
                ldsm4(a0, qbase + ks * 32);
                ldsm4(a1, qbase + 16 * QS_STR * 2 + ks * 32);
                unsigned kb[2][4];
#pragma unroll
                for (int p = 0; p < 2; p++)
                    ldsm4(kb[p], kbase + (wn * 32 + p * 16) * KS_STR * 2 + ks * 32);
#pragma unroll
                for (int p = 0; p < 2; p++) {
                    mma16816(sc[0][2 * p],     a0, kb[p][0], kb[p][1]);
                    mma16816(sc[0][2 * p + 1], a0, kb[p][2], kb[p][3]);
                    mma16816(sc[1][2 * p],     a1, kb[p][0], kb[p][1]);
                    mma16816(sc[1][2 * p + 1], a1, kb[p][2], kb[p][3]);
                }
            }
        }

        // ---- additive mask bias + scale, row max
        float rmax[2][2] = {{-INFINITY, -INFINITY}, {-INFINITY, -INFINITY}};
        const __half* Bb = Bg + (size_t)b * NS * NS + (size_t)q0 * NS + t0;
#pragma unroll
        for (int mt = 0; mt < 2; mt++) {
            int rl = wm * 32 + mt * 16 + g;
#pragma unroll
            for (int nt = 0; nt < 4; nt++) {
                int cl = wn * 32 + nt * 8 + 2 * t;
                const __half* mp = Bb + (size_t)rl * NS + cl;
                float2 f0 = __half22float2(*(const __half2*)mp);
                float2 f1 = __half22float2(*(const __half2*)(mp + 8 * NS));
                float s0 = fmaf(sc[mt][nt][0], scale, f0.x);
                float s1 = fmaf(sc[mt][nt][1], scale, f0.y);
                float s2 = fmaf(sc[mt][nt][2], scale, f1.x);
                float s3 = fmaf(sc[mt][nt][3], scale, f1.y);
                sc[mt][nt][0] = s0; sc[mt][nt][1] = s1;
                sc[mt][nt][2] = s2; sc[mt][nt][3] = s3;
                rmax[mt][0] = fmaxf(rmax[mt][0], fmaxf(s0, s1));
                rmax[mt][1] = fmaxf(rmax[mt][1], fmaxf(s2, s3));
            }
        }
#pragma unroll
        for (int mt = 0; mt < 2; mt++)
#pragma unroll
            for (int hh = 0; hh < 2; hh++) {
                float v = rmax[mt][hh];
                v = fmaxf(v, __shfl_xor_sync(0xffffffffu, v, 1));
                v = fmaxf(v, __shfl_xor_sync(0xffffffffu, v, 2));
                rmax[mt][hh] = v;
            }
        if (t == 0) {
#pragma unroll
            for (int mt = 0; mt < 2; mt++)
#pragma unroll
                for (int hh = 0; hh < 2; hh++)
                    smf[SOFF_RMAX + wn * 128 + wm * 32 + mt * 16 + g + 8 * hh] = rmax[mt][hh];
        }
        __syncthreads();

        float mold[2][2], mnew[2][2];
#pragma unroll
        for (int mt = 0; mt < 2; mt++)
#pragma unroll
            for (int hh = 0; hh < 2; hh++) {
                int r = wm * 32 + mt * 16 + g + 8 * hh;
                float tm = fmaxf(smf[SOFF_RMAX + r], smf[SOFF_RMAX + 128 + r]);
                mold[mt][hh] = smf[SOFF_M + r];
                mnew[mt][hh] = fmaxf(mold[mt][hh], tm);
            }
        float rsum[2][2] = {{0.f, 0.f}, {0.f, 0.f}};
#pragma unroll
        for (int mt = 0; mt < 2; mt++)
#pragma unroll
            for (int nt = 0; nt < 4; nt++) {
                float e0 = __expf(sc[mt][nt][0] - mnew[mt][0]);
                float e1 = __expf(sc[mt][nt][1] - mnew[mt][0]);
                float e2 = __expf(sc[mt][nt][2] - mnew[mt][1]);
                float e3 = __expf(sc[mt][nt][3] - mnew[mt][1]);
                rsum[mt][0] += e0 + e1;
                rsum[mt][1] += e2 + e3;
                int r0 = wm * 32 + mt * 16 + g;
                int cl = wn * 32 + nt * 8 + 2 * t;
                *(unsigned*)&smh[OFF_P + r0 * PS_STR + cl]       = h2pack(e0, e1);
                *(unsigned*)&smh[OFF_P + (r0 + 8) * PS_STR + cl] = h2pack(e2, e3);
            }
#pragma unroll
        for (int mt = 0; mt < 2; mt++)
#pragma unroll
            for (int hh = 0; hh < 2; hh++) {
                float v = rsum[mt][hh];
                v += __shfl_xor_sync(0xffffffffu, v, 1);
                v += __shfl_xor_sync(0xffffffffu, v, 2);
                rsum[mt][hh] = v;
            }
        if (t == 0) {
#pragma unroll
            for (int mt = 0; mt < 2; mt++)
#pragma unroll
                for (int hh = 0; hh < 2; hh++)
                    smf[SOFF_RSUM + wn * 128 + wm * 32 + mt * 16 + g + 8 * hh] = rsum[mt][hh];
        }
#pragma unroll
        for (int mt = 0; mt < 2; mt++) {
            float c0 = __expf(mold[mt][0] - mnew[mt][0]);
            float c1 = __expf(mold[mt][1] - mnew[mt][1]);
#pragma unroll
            for (int nt = 0; nt < 8; nt++) {
                accz[mt][nt][0] *= c0; accz[mt][nt][1] *= c0;
                accz[mt][nt][2] *= c1; accz[mt][nt][3] *= c1;
            }
        }
        __syncthreads();

        if (tid < 128) {
            int r = tid;
            float tm = fmaxf(smf[SOFF_RMAX + r], smf[SOFF_RMAX + 128 + r]);
            float mo = smf[SOFF_M + r];
            float mn = fmaxf(mo, tm);
            float corr = __expf(mo - mn);
            smf[SOFF_L + r] = smf[SOFF_L + r] * corr +
                              smf[SOFF_RSUM + r] + smf[SOFF_RSUM + 128 + r];
            smf[SOFF_M + r] = mn;
        }

        {
            unsigned pbase = sptr(smh + OFF_P) +
                ((wm * 32 + (lane & 15)) * PS_STR + (lane >> 4) * 8) * 2;
            unsigned vbase = sptr(smh + OFF_V) +
                ((lane & 15) * VS_STR + wn * 64 + (lane >> 4) * 8) * 2;
#pragma unroll
            for (int ks = 0; ks < 4; ks++) {
                unsigned a0[4], a1[4];
                ldsm4(a0, pbase + ks * 32);
                ldsm4(a1, pbase + 16 * PS_STR * 2 + ks * 32);
                unsigned vf[4][4];
#pragma unroll
                for (int p = 0; p < 4; p++)
                    ldsm4t(vf[p], vbase + ks * 16 * VS_STR * 2 + p * 32);
#pragma unroll
                for (int p = 0; p < 4; p++) {
                    mma16816(accz[0][2 * p],     a0, vf[p][0], vf[p][1]);
                    mma16816(accz[0][2 * p + 1], a0, vf[p][2], vf[p][3]);
                    mma16816(accz[1][2 * p],     a1, vf[p][0], vf[p][1]);
                    mma16816(accz[1][2 * p + 1], a1, vf[p][2], vf[p][3]);
                }
            }
        }
    }

    __syncthreads();
#pragma unroll
    for (int mt = 0; mt < 2; mt++) {
        int r0 = wm * 32 + mt * 16 + g;
        float inv0 = 1.0f / smf[SOFF_L + r0];
        float inv1 = 1.0f / smf[SOFF_L + r0 + 8];
#pragma unroll
        for (int nt = 0; nt < 8; nt++) {
            int col = wn * 64 + nt * 8 + 2 * t;
            __half* d0 = Og + ((size_t)(b * NS + q0 + r0)) * ND + h * NK + col;
            *(unsigned*)(d0)          = h2pack(accz[mt][nt][0] * inv0, accz[mt][nt][1] * inv0);
            *(unsigned*)(d0 + 8 * ND) = h2pack(accz[mt][nt][2] * inv1, accz[mt][nt][3] * inv1);
        }
    }
}

// ---------------- fused residual add + LayerNorm -----------------------------
__global__ __launch_bounds__(256) void add_ln_kernel(
    const float* __restrict__ X, const float* __restrict__ R,
    const float* __restrict__ ga, const float* __restrict__ be,
    float* __restrict__ O, __half* __restrict__ O16)
{
    __shared__ float red1[8];
    __shared__ float red2[8];
    __shared__ float s_mean, s_rstd;
    const int row = blockIdx.x;
    const int tid = threadIdx.x;
    const size_t base = (size_t)row * ND;

    float4 a = *(const float4*)(X + base + tid * 4);
    float4 r = *(const float4*)(R + base + tid * 4);
    float v0 = a.x + r.x, v1 = a.y + r.y, v2 = a.z + r.z, v3 = a.w + r.w;

    float s = v0 + v1 + v2 + v3;
#pragma unroll
    for (int o = 16; o > 0; o >>= 1) s += __shfl_xor_sync(0xffffffffu, s, o);
    if ((tid & 31) == 0) red1[tid >> 5] = s;
    __syncthreads();
    if (tid == 0) {
        float tt = 0.f;
#pragma unroll
        for (int i = 0; i < 8; i++) tt += red1[i];
        s_mean = tt * (1.0f / ND);
    }
    __syncthreads();
    const float mean = s_mean;
    float d0 = v0 - mean, d1 = v1 - mean, d2 = v2 - mean, d3 = v3 - mean;
    float q = d0 * d0 + d1 * d1 + d2 * d2 + d3 * d3;
#pragma unroll
    for (int o = 16; o > 0; o >>= 1) q += __shfl_xor_sync(0xffffffffu, q, o);
    if ((tid & 31) == 0) red2[tid >> 5] = q;
    __syncthreads();
    if (tid == 0) {
        float tt = 0.f;
#pragma unroll
        for (int i = 0; i < 8; i++) tt += red2[i];
        s_rstd = rsqrtf(tt * (1.0f / ND) + 1e-5f);
    }
    __syncthreads();
    const float rstd = s_rstd;

    float4 g4 = *(const float4*)(ga + tid * 4);
    float4 b4 = *(const float4*)(be + tid * 4);
    float4 o4;
    o4.x = d0 * rstd * g4.x + b4.x;
    o4.y = d1 * rstd * g4.y + b4.y;
    o4.z = d2 * rstd * g4.z + b4.z;
    o4.w = d3 * rstd * g4.w + b4.w;
    *(float4*)(O + base + tid * 4) = o4;
    uint2 hh; hh.x = h2pack(o4.x, o4.y); hh.y = h2pack(o4.z, o4.w);
    *(uint2*)(O16 + base + tid * 4) = hh;
}

// ---------------- launcher ---------------------------------------------------
extern "C" void kernel_launch(void* const* d_in, const int* in_sizes, int n_in,
                              void* d_out, int out_size) {
    (void)in_sizes; (void)n_in; (void)out_size;
    const float* x    = (const float*)d_in[0];
    const int*   mask = (const int*)  d_in[1];
    const float* wq   = (const float*)d_in[2];
    const float* bq   = (const float*)d_in[3];
    const float* wk   = (const float*)d_in[4];
    const float* bk   = (const float*)d_in[5];
    const float* wv   = (const float*)d_in[6];
    const float* bv   = (const float*)d_in[7];
    const float* wo   = (const float*)d_in[8];
    const float* bo   = (const float*)d_in[9];
    const float* w1   = (const float*)d_in[10];
    const float* b1   = (const float*)d_in[11];
    const float* w2   = (const float*)d_in[12];
    const float* b2   = (const float*)d_in[13];
    const float* l1g  = (const float*)d_in[14];
    const float* l1b  = (const float*)d_in[15];
    const float* l2g  = (const float*)d_in[16];
    const float* l2b  = (const float*)d_in[17];

    float *px, *pt1;
    __half *px16, *pq, *pk, *pv, *pao, *ph, *pwtd, *pwtq, *pmb;
    cudaGetSymbolAddress((void**)&px,   g_x);
    cudaGetSymbolAddress((void**)&pt1,  g_t1);
    cudaGetSymbolAddress((void**)&px16, g_x16);
    cudaGetSymbolAddress((void**)&pq,   g_q);
    cudaGetSymbolAddress((void**)&pk,   g_k);
    cudaGetSymbolAddress((void**)&pv,   g_v);
    cudaGetSymbolAddress((void**)&pao,  g_ao);
    cudaGetSymbolAddress((void**)&ph,   g_h);
    cudaGetSymbolAddress((void**)&pwtd, g_wtd);
    cudaGetSymbolAddress((void**)&pwtq, g_wtq);
    cudaGetSymbolAddress((void**)&pmb,  g_mb);

    cudaFuncSetAttribute(gemm_v3, cudaFuncAttributeMaxDynamicSharedMemorySize, GEMM_SMEM_BYTES);
    cudaFuncSetAttribute(attn_f16, cudaFuncAttributeMaxDynamicSharedMemorySize, ATTN_SMEM_BYTES);

    tr_dense<<<dim3(32, 32, 12), dim3(32, 8)>>>(wo, w1, w2, pwtd);
    tr_qkv  <<<dim3(4,  32, 96), dim3(32, 8)>>>(wq, wk, wv, pwtq);
    prep_mask<<<(size_t)NB * NS * NS / 4 / 256, 256>>>((const int4*)mask, (uint2*)pmb);

    copy_in<<<(NM * ND / 4) / 256, 256>>>((const float4*)x, (float4*)px, (uint2*)px16);

    const dim3 ggrid(ND / 128, NM / 256);       // (8, 32)
    const dim3 gqkv (ND / 128, NM / 256, 3);

    for (int l = 0; l < NL; l++) {
        const size_t vof = (size_t)l * ND;
        const size_t qb  = (size_t)l * NH * NK;

        gemm_v3<<<gqkv, 256, GEMM_SMEM_BYTES>>>(
            px16, pwtq + (size_t)l * 3 * ND * ND,
            bq + qb, bk + qb, bv + qb,
            (float*)0, pq, pk, pv, 2);

        attn_f16<<<dim3(NS / 128, NB * NH), 256, ATTN_SMEM_BYTES>>>(
            pq, pk, pv, pmb, pao);

        gemm_v3<<<ggrid, 256, GEMM_SMEM_BYTES>>>(
            pao, pwtd + (size_t)(l * 3 + 0) * ND * ND,
            bo + vof, (float*)0, (float*)0, pt1, (__half*)0, (__half*)0, (__half*)0, 0);
        add_ln_kernel<<<NM, 256>>>(px, pt1, l1g + vof, l1b + vof, px, px16);

        gemm_v3<<<ggrid, 256, GEMM_SMEM_BYTES>>>(
            px16, pwtd + (size_t)(l * 3 + 1) * ND * ND,
            b1 + vof, (float*)0, (float*)0, (float*)0, ph, (__half*)0, (__half*)0, 1);
        gemm_v3<<<ggrid, 256, GEMM_SMEM_BYTES>>>(
            ph, pwtd + (size_t)(l * 3 + 2) * ND * ND,
            b2 + vof, (float*)0, (float*)0, pt1, (__half*)0, (__half*)0, (__half*)0, 0);

        float* dst = (l == NL - 1) ? (float*)d_out : px;
        add_ln_kernel<<<NM, 256>>>(px, pt1, l2g + vof, l2b + vof, dst, px16);
    }
}

// round 7
// speedup vs baseline: 1.0974x; 1.0974x over previous
#include <cuda_runtime.h>
#include <cuda_fp16.h>
#include <math.h>
#include <stdint.h>

#define NB 4
#define NS 2048
#define ND 1024
#define NH 8
#define NK 128
#define NL 4
#define NM (NB*NS)

// ---------------- scratch ----------------------------------------------------
__device__ float  g_x  [NM*ND];
__device__ float  g_t1 [NM*ND];
__device__ __half g_x16[NM*ND];
__device__ __half g_q  [NM*ND];
__device__ __half g_k  [NM*ND];
__device__ __half g_v  [NM*ND];
__device__ __half g_ao [NM*ND];
__device__ __half g_h  [NM*ND];
__device__ __half g_wtd[12*ND*ND];      // dense weights transposed [l][3][N][K] f16
__device__ __half g_wtq[12*ND*ND];      // qkv weights  transposed [l][3][H*128][K] f16

// ---------------- helpers ----------------------------------------------------
__device__ __forceinline__ float gelu_exact(float x) {
    return 0.5f * x * (1.0f + erff(x * 0.7071067811865476f));
}
__device__ __forceinline__ unsigned sptr(const void* p) {
    return (unsigned)__cvta_generic_to_shared(p);
}
__device__ __forceinline__ unsigned h2pack(float x, float y) {
    __half2 h = __floats2half2_rn(x, y);
    return *(unsigned*)&h;
}
__device__ __forceinline__ void ldsm4(unsigned r[4], unsigned a) {
    asm volatile("ldmatrix.sync.aligned.m8n8.x4.shared.b16 {%0,%1,%2,%3}, [%4];\n"
        : "=r"(r[0]), "=r"(r[1]), "=r"(r[2]), "=r"(r[3]) : "r"(a));
}
__device__ __forceinline__ void ldsm4t(unsigned r[4], unsigned a) {
    asm volatile("ldmatrix.sync.aligned.m8n8.x4.trans.shared.b16 {%0,%1,%2,%3}, [%4];\n"
        : "=r"(r[0]), "=r"(r[1]), "=r"(r[2]), "=r"(r[3]) : "r"(a));
}
__device__ __forceinline__ void mma16816(float c[4], const unsigned a[4],
                                         unsigned b0, unsigned b1) {
    asm volatile("mma.sync.aligned.m16n8k16.row.col.f32.f16.f16.f32 "
        "{%0,%1,%2,%3}, {%4,%5,%6,%7}, {%8,%9}, {%0,%1,%2,%3};\n"
        : "+f"(c[0]), "+f"(c[1]), "+f"(c[2]), "+f"(c[3])
        : "r"(a[0]), "r"(a[1]), "r"(a[2]), "r"(a[3]), "r"(b0), "r"(b1));
}
#define CP16(dst, src) \
    asm volatile("cp.async.cg.shared.global [%0], [%1], 16;" :: "r"(dst), "l"(src) : "memory")
#define CP_COMMIT() asm volatile("cp.async.commit_group;" ::: "memory")

__global__ void copy_in(const float4* __restrict__ s, float4* __restrict__ dx,
                        uint2* __restrict__ dh) {
    int i = blockIdx.x * blockDim.x + threadIdx.x;
    float4 v = s[i];
    dx[i] = v;
    uint2 hh; hh.x = h2pack(v.x, v.y); hh.y = h2pack(v.z, v.w);
    dh[i] = hh;
}

// ---------------- weight transposes (f32 [K][N] -> f16 [N][K]) --------------
__global__ void tr_dense(const float* __restrict__ wo, const float* __restrict__ w1,
                         const float* __restrict__ w2, __half* __restrict__ dst) {
    __shared__ float tile[32][33];
    int z = blockIdx.z, l = z / 3, which = z % 3;
    const float* W = (which == 0 ? wo : which == 1 ? w1 : w2) + (size_t)l * ND * ND;
    __half* D = dst + (size_t)z * ND * ND;
    int n0 = blockIdx.x * 32, k0 = blockIdx.y * 32;
    int tx = threadIdx.x, ty = threadIdx.y;
#pragma unroll
    for (int i = 0; i < 32; i += 8)
        tile[ty + i][tx] = W[(size_t)(k0 + ty + i) * ND + n0 + tx];
    __syncthreads();
#pragma unroll
    for (int i = 0; i < 32; i += 8)
        D[(size_t)(n0 + ty + i) * ND + k0 + tx] = __float2half_rn(tile[tx][ty + i]);
}

__global__ void tr_qkv(const float* __restrict__ wq, const float* __restrict__ wk,
                       const float* __restrict__ wv, __half* __restrict__ dst) {
    __shared__ float tile[32][33];
    int z = blockIdx.z;                 // (l*3+sel)*8 + h
    int l = z / 24, rem = z % 24, sel = rem / 8, h = rem % 8;
    const float* W = (sel == 0 ? wq : sel == 1 ? wk : wv) + (size_t)(l * NH + h) * ND * NK;
    __half* D = dst + (size_t)((l * 3 + sel) * 8 + h) * NK * ND;
    int n0 = blockIdx.x * 32, k0 = blockIdx.y * 32;
    int tx = threadIdx.x, ty = threadIdx.y;
#pragma unroll
    for (int i = 0; i < 32; i += 8)
        tile[ty + i][tx] = W[(size_t)(k0 + ty + i) * NK + n0 + tx];
    __syncthreads();
#pragma unroll
    for (int i = 0; i < 32; i += 8)
        D[(size_t)(n0 + ty + i) * ND + k0 + tx] = __float2half_rn(tile[tx][ty + i]);
}

// ============================================================================
// GEMM v4: block 128x128, 128 threads (4 warps), warp 64x64, K-chunk 32,
// 3-stage cp.async pipeline (ONE barrier per chunk), XOR-swizzled 64B rows.
// mode: 0 = f32 out, 1 = half+gelu, 2 = qkv scatter (gridDim.z selects W/b/out)
// ============================================================================
#define BK 32
#define STG 3
#define ASZ (128*BK)                          // halfs per A (or B) stage
#define NCH (ND/BK)                           // 32 chunks
#define GEMM_SMEM_BYTES (STG*2*ASZ*2)         // 48 KB

__global__ __launch_bounds__(128, 2) void gemm_v4(
    const __half* __restrict__ A, const __half* __restrict__ BtBase,
    const float* __restrict__ bias0, const float* __restrict__ bias1,
    const float* __restrict__ bias2,
    float* __restrict__ Cf, __half* __restrict__ Ch0,
    __half* __restrict__ Ch1, __half* __restrict__ Ch2, int mode)
{
    extern __shared__ __half smh[];
    __half* sA = smh;                         // [STG][128][32]
    __half* sB = smh + STG * ASZ;             // [STG][128][32]

    const int tid = threadIdx.x, lane = tid & 31, wid = tid >> 5;
    const int wm = wid >> 1, wn = wid & 1, g = lane >> 2, t = lane & 3;
    const int m0 = blockIdx.y * 128, n0 = blockIdx.x * 128;

    const int sel = blockIdx.z;
    const __half* Bt = BtBase + (size_t)sel * ND * ND;
    const float* bias = (sel == 0) ? bias0 : (sel == 1) ? bias1 : bias2;
    __half* Ch = (sel == 0) ? Ch0 : (sel == 1) ? Ch1 : Ch2;

    float c[4][8][4];
#pragma unroll
    for (int mt = 0; mt < 4; mt++)
#pragma unroll
        for (int nt = 0; nt < 8; nt++)
#pragma unroll
            for (int i = 0; i < 4; i++) c[mt][nt][i] = 0.f;

    const int lr = tid >> 2;                  // row 0..31 (x4 strided)
    const int lu = tid & 3;                   // 16B unit
    const unsigned sA0 = sptr(sA), sB0 = sptr(sB);

    const int arow = wm * 64 + (lane & 15);
    const int axor = (arow >> 1) & 3;
    const int ahi  = lane >> 4;
    const int brow = (lane >> 4) * 8 + (lane & 7);
    const int bxor = (brow >> 1) & 3;
    const int bhi  = (lane >> 3) & 1;

#define LOAD_CHUNK(ck, st) do {                                               \
    int _k0 = (ck) * BK;                                                      \
    _Pragma("unroll")                                                         \
    for (int _i = 0; _i < 4; _i++) {                                          \
        int _r = lr + _i * 32;                                                \
        unsigned _sw = ((unsigned)(lu ^ ((_r >> 1) & 3))) * 16;               \
        CP16(sA0 + (st) * ASZ * 2 + _r * 64 + _sw,                            \
             A + (size_t)(m0 + _r) * ND + _k0 + lu * 8);                      \
        CP16(sB0 + (st) * ASZ * 2 + _r * 64 + _sw,                            \
             Bt + (size_t)(n0 + _r) * ND + _k0 + lu * 8);                     \
    }                                                                         \
    CP_COMMIT();                                                              \
} while (0)

    LOAD_CHUNK(0, 0);
    LOAD_CHUNK(1, 1);

    int st = 0;
    for (int ck = 0; ck < NCH; ck++) {
        if (ck + 2 < NCH) {
            asm volatile("cp.async.wait_group 1;" ::: "memory");
        } else {
            asm volatile("cp.async.wait_group 0;" ::: "memory");
        }
        __syncthreads();
        if (ck + 2 < NCH) {
            int st2 = st + 2; if (st2 >= STG) st2 -= STG;
            LOAD_CHUNK(ck + 2, st2);
        }

        unsigned abuf = sA0 + st * ASZ * 2;
        unsigned bbuf = sB0 + st * ASZ * 2;
#pragma unroll
        for (int ks = 0; ks < 2; ks++) {
            unsigned akoff = ((unsigned)((ks * 2 + ahi) ^ axor)) * 16;
            unsigned a[4][4];
#pragma unroll
            for (int mt = 0; mt < 4; mt++)
                ldsm4(a[mt], abuf + (arow + mt * 16) * 64 + akoff);
            unsigned bkoff = ((unsigned)((ks * 2 + bhi) ^ bxor)) * 16;
#pragma unroll
            for (int p = 0; p < 4; p++) {
                unsigned bf[4];
                ldsm4(bf, bbuf + (brow + wn * 64 + p * 16) * 64 + bkoff);
#pragma unroll
                for (int mt = 0; mt < 4; mt++) {
                    mma16816(c[mt][2 * p],     a[mt], bf[0], bf[1]);
                    mma16816(c[mt][2 * p + 1], a[mt], bf[2], bf[3]);
                }
            }
        }
        if (++st >= STG) st -= STG;
    }

    // epilogue
#pragma unroll
    for (int mt = 0; mt < 4; mt++) {
        int r0 = m0 + wm * 64 + mt * 16 + g;
#pragma unroll
        for (int nt = 0; nt < 8; nt++) {
            int col = n0 + wn * 64 + nt * 8 + 2 * t;
            float b0 = bias[col], b1 = bias[col + 1];
            float v0 = c[mt][nt][0] + b0, v1 = c[mt][nt][1] + b1;
            float v2 = c[mt][nt][2] + b0, v3 = c[mt][nt][3] + b1;
            if (mode == 0) {
                *(float2*)(Cf + (size_t)r0 * ND + col)       = make_float2(v0, v1);
                *(float2*)(Cf + (size_t)(r0 + 8) * ND + col) = make_float2(v2, v3);
            } else if (mode == 1) {
                v0 = gelu_exact(v0); v1 = gelu_exact(v1);
                v2 = gelu_exact(v2); v3 = gelu_exact(v3);
                *(unsigned*)(Ch + (size_t)r0 * ND + col)       = h2pack(v0, v1);
                *(unsigned*)(Ch + (size_t)(r0 + 8) * ND + col) = h2pack(v2, v3);
            } else {
                int head = col >> 7, within = col & 127;
                int bb0 = r0 >> 11, s0 = r0 & (NS - 1);
                __half* d0 = Ch + ((size_t)(bb0 * NH + head) * NS + s0) * NK + within;
                *(unsigned*)(d0)          = h2pack(v0, v1);
                *(unsigned*)(d0 + 8 * NK) = h2pack(v2, v3);
            }
        }
    }
}

// ============================================================================
// Flash attention fp16 SIMT tensor core (R5-proven, int32 mask)
// ============================================================================
#define QS_STR 136
#define KS_STR 136
#define VS_STR 136
#define PS_STR 72
#define OFF_Q 0
#define OFF_K (128*QS_STR)
#define OFF_V (OFF_K + 64*KS_STR)
#define OFF_P (OFF_V + 64*VS_STR)
#define HALF_END (OFF_P + 128*PS_STR)
#define SOFF_M    0
#define SOFF_L    128
#define SOFF_RMAX 256
#define SOFF_RSUM 512
#define ATTN_SMEM_BYTES (HALF_END*2 + 768*4)

__global__ __launch_bounds__(256) void attn_f16(
    const __half* __restrict__ Qg, const __half* __restrict__ Kg,
    const __half* __restrict__ Vg, const int* __restrict__ Mg,
    __half* __restrict__ Og)
{
    extern __shared__ __half smh[];
    float* smf = (float*)((char*)smh + HALF_END * 2);

    const int tid = threadIdx.x, lane = tid & 31, w = tid >> 5;
    const int wm = w >> 1, wn = w & 1, g = lane >> 2, t = lane & 3;
    const int bh = blockIdx.y, b = bh >> 3, h = bh & 7;
    const int q0 = blockIdx.x * 128;

    const __half* Qb = Qg + ((size_t)bh * NS + q0) * NK;
#pragma unroll
    for (int i = 0; i < 8; i++) {
        int idx = tid + i * 256;
        int r = idx >> 4, c8 = (idx & 15) * 8;
        *(uint4*)&smh[OFF_Q + r * QS_STR + c8] = *(const uint4*)(Qb + (size_t)r * NK + c8);
    }
    if (tid < 128) { smf[SOFF_M + tid] = -INFINITY; smf[SOFF_L + tid] = 0.f; }

    float accz[2][8][4];
#pragma unroll
    for (int mt = 0; mt < 2; mt++)
#pragma unroll
        for (int nt = 0; nt < 8; nt++)
#pragma unroll
            for (int i = 0; i < 4; i++) accz[mt][nt][i] = 0.f;

    const float scale = 0.08838834764831845f;

    for (int t0 = 0; t0 < NS; t0 += 64) {
        __syncthreads();
        const __half* Kb = Kg + ((size_t)bh * NS + t0) * NK;
        const __half* Vb = Vg + ((size_t)bh * NS + t0) * NK;
#pragma unroll
        for (int i = 0; i < 4; i++) {
            int idx = tid + i * 256;
            int r = idx >> 4, c8 = (idx & 15) * 8;
            *(uint4*)&smh[OFF_K + r * KS_STR + c8] = *(const uint4*)(Kb + (size_t)r * NK + c8);
            *(uint4*)&smh[OFF_V + r * VS_STR + c8] = *(const uint4*)(Vb + (size_t)r * NK + c8);
        }
        __syncthreads();

        float sc[2][4][4];
#pragma unroll
        for (int mt = 0; mt < 2; mt++)
#pragma unroll
            for (int nt = 0; nt < 4; nt++)
#pragma unroll
                for (int i = 0; i < 4; i++) sc[mt][nt][i] = 0.f;

        {
            unsigned qbase = sptr(smh + OFF_Q) +
                ((wm * 32 + (lane & 15)) * QS_STR + (lane >> 4) * 8) * 2;
            unsigned kbase = sptr(smh + OFF_K) +
                (((lane >> 4) * 8 + (lane & 7)) * KS_STR + ((lane >> 3) & 1) * 8) * 2;
#pragma unroll
            for (int ks = 0; ks < 8; ks++) {
                unsigned a0[4], a1[4];
                ldsm4(a0, qbase + ks * 32);
                ldsm4(a1, qbase + 16 * QS_STR * 2 + ks * 32);
                unsigned kb[2][4];
#pragma unroll
                for (int p = 0; p < 2; p++)
                    ldsm4(kb[p], kbase + (wn * 32 + p * 16) * KS_STR * 2 + ks * 32);
#pragma unroll
                for (int p = 0; p < 2; p++) {
                    mma16816(sc[0][2 * p],     a0, kb[p][0], kb[p][1]);
                    mma16816(sc[0][2 * p + 1], a0, kb[p][2], kb[p][3]);
                    mma16816(sc[1][2 * p],     a1, kb[p][0], kb[p][1]);
                    mma16816(sc[1][2 * p + 1], a1, kb[p][2], kb[p][3]);
                }
            }
        }

        float rmax[2][2] = {{-INFINITY, -INFINITY}, {-INFINITY, -INFINITY}};
        const size_t mbase = (size_t)b * NS * NS + (size_t)q0 * NS + t0;
#pragma unroll
        for (int mt = 0; mt < 2; mt++) {
            int rl = wm * 32 + mt * 16 + g;
#pragma unroll
            for (int nt = 0; nt < 4; nt++) {
                int cl = wn * 32 + nt * 8 + 2 * t;
                const int* mp = Mg + mbase + (size_t)rl * NS + cl;
                int2 mv0 = *(const int2*)mp;
                int2 mv1 = *(const int2*)(mp + 8 * NS);
                float s0 = (mv0.x == 0) ? -1.0e9f : sc[mt][nt][0] * scale;
                float s1 = (mv0.y == 0) ? -1.0e9f : sc[mt][nt][1] * scale;
                float s2 = (mv1.x == 0) ? -1.0e9f : sc[mt][nt][2] * scale;
                float s3 = (mv1.y == 0) ? -1.0e9f : sc[mt][nt][3] * scale;
                sc[mt][nt][0] = s0; sc[mt][nt][1] = s1;
                sc[mt][nt][2] = s2; sc[mt][nt][3] = s3;
                rmax[mt][0] = fmaxf(rmax[mt][0], fmaxf(s0, s1));
                rmax[mt][1] = fmaxf(rmax[mt][1], fmaxf(s2, s3));
            }
        }
#pragma unroll
        for (int mt = 0; mt < 2; mt++)
#pragma unroll
            for (int hh = 0; hh < 2; hh++) {
                float v = rmax[mt][hh];
                v = fmaxf(v, __shfl_xor_sync(0xffffffffu, v, 1));
                v = fmaxf(v, __shfl_xor_sync(0xffffffffu, v, 2));
                rmax[mt][hh] = v;
            }
        if (t == 0) {
#pragma unroll
            for (int mt = 0; mt < 2; mt++)
#pragma unroll
                for (int hh = 0; hh < 2; hh++)
                    smf[SOFF_RMAX + wn * 128 + wm * 32 + mt * 16 + g + 8 * hh] = rmax[mt][hh];
        }
        __syncthreads();

        float mold[2][2], mnew[2][2];
#pragma unroll
        for (int mt = 0; mt < 2; mt++)
#pragma unroll
            for (int hh = 0; hh < 2; hh++) {
                int r = wm * 32 + mt * 16 + g + 8 * hh;
                float tm = fmaxf(smf[SOFF_RMAX + r], smf[SOFF_RMAX + 128 + r]);
                mold[mt][hh] = smf[SOFF_M + r];
                mnew[mt][hh] = fmaxf(mold[mt][hh], tm);
            }
        float rsum[2][2] = {{0.f, 0.f}, {0.f, 0.f}};
#pragma unroll
        for (int mt = 0; mt < 2; mt++)
#pragma unroll
            for (int nt = 0; nt < 4; nt++) {
                float e0 = __expf(sc[mt][nt][0] - mnew[mt][0]);
                float e1 = __expf(sc[mt][nt][1] - mnew[mt][0]);
                float e2 = __expf(sc[mt][nt][2] - mnew[mt][1]);
                float e3 = __expf(sc[mt][nt][3] - mnew[mt][1]);
                rsum[mt][0] += e0 + e1;
                rsum[mt][1] += e2 + e3;
                int r0 = wm * 32 + mt * 16 + g;
                int cl = wn * 32 + nt * 8 + 2 * t;
                *(unsigned*)&smh[OFF_P + r0 * PS_STR + cl]       = h2pack(e0, e1);
                *(unsigned*)&smh[OFF_P + (r0 + 8) * PS_STR + cl] = h2pack(e2, e3);
            }
#pragma unroll
        for (int mt = 0; mt < 2; mt++)
#pragma unroll
            for (int hh = 0; hh < 2; hh++) {
                float v = rsum[mt][hh];
                v += __shfl_xor_sync(0xffffffffu, v, 1);
                v += __shfl_xor_sync(0xffffffffu, v, 2);
                rsum[mt][hh] = v;
            }
        if (t == 0) {
#pragma unroll
            for (int mt = 0; mt < 2; mt++)
#pragma unroll
                for (int hh = 0; hh < 2; hh++)
                    smf[SOFF_RSUM + wn * 128 + wm * 32 + mt * 16 + g + 8 * hh] = rsum[mt][hh];
        }
#pragma unroll
        for (int mt = 0; mt < 2; mt++) {
            float c0 = __expf(mold[mt][0] - mnew[mt][0]);
            float c1 = __expf(mold[mt][1] - mnew[mt][1]);
#pragma unroll
            for (int nt = 0; nt < 8; nt++) {
                accz[mt][nt][0] *= c0; accz[mt][nt][1] *= c0;
                accz[mt][nt][2] *= c1; accz[mt][nt][3] *= c1;
            }
        }
        __syncthreads();

        if (tid < 128) {
            int r = tid;
            float tm = fmaxf(smf[SOFF_RMAX + r], smf[SOFF_RMAX + 128 + r]);
            float mo = smf[SOFF_M + r];
            float mn = fmaxf(mo, tm);
            float corr = __expf(mo - mn);
            smf[SOFF_L + r] = smf[SOFF_L + r] * corr +
                              smf[SOFF_RSUM + r] + smf[SOFF_RSUM + 128 + r];
            smf[SOFF_M + r] = mn;
        }

        {
            unsigned pbase = sptr(smh + OFF_P) +
                ((wm * 32 + (lane & 15)) * PS_STR + (lane >> 4) * 8) * 2;
            unsigned vbase = sptr(smh + OFF_V) +
                ((lane & 15) * VS_STR + wn * 64 + (lane >> 4) * 8) * 2;
#pragma unroll
            for (int ks = 0; ks < 4; ks++) {
                unsigned a0[4], a1[4];
                ldsm4(a0, pbase + ks * 32);
                ldsm4(a1, pbase + 16 * PS_STR * 2 + ks * 32);
                unsigned vf[4][4];
#pragma unroll
                for (int p = 0; p < 4; p++)
                    ldsm4t(vf[p], vbase + ks * 16 * VS_STR * 2 + p * 32);
#pragma unroll
                for (int p = 0; p < 4; p++) {
                    mma16816(accz[0][2 * p],     a0, vf[p][0], vf[p][1]);
                    mma16816(accz[0][2 * p + 1], a0, vf[p][2], vf[p][3]);
                    mma16816(accz[1][2 * p],     a1, vf[p][0], vf[p][1]);
                    mma16816(accz[1][2 * p + 1], a1, vf[p][2], vf[p][3]);
                }
            }
        }
    }

    __syncthreads();
#pragma unroll
    for (int mt = 0; mt < 2; mt++) {
        int r0 = wm * 32 + mt * 16 + g;
        float inv0 = 1.0f / smf[SOFF_L + r0];
        float inv1 = 1.0f / smf[SOFF_L + r0 + 8];
#pragma unroll
        for (int nt = 0; nt < 8; nt++) {
            int col = wn * 64 + nt * 8 + 2 * t;
            __half* d0 = Og + ((size_t)(b * NS + q0 + r0)) * ND + h * NK + col;
            *(unsigned*)(d0)          = h2pack(accz[mt][nt][0] * inv0, accz[mt][nt][1] * inv0);
            *(unsigned*)(d0 + 8 * ND) = h2pack(accz[mt][nt][2] * inv1, accz[mt][nt][3] * inv1);
        }
    }
}

// ---------------- fused residual add + LayerNorm -----------------------------
__global__ __launch_bounds__(256) void add_ln_kernel(
    const float* __restrict__ X, const float* __restrict__ R,
    const float* __restrict__ ga, const float* __restrict__ be,
    float* __restrict__ O, __half* __restrict__ O16)
{
    __shared__ float red1[8];
    __shared__ float red2[8];
    __shared__ float s_mean, s_rstd;
    const int row = blockIdx.x;
    const int tid = threadIdx.x;
    const size_t base = (size_t)row * ND;

    float4 a = *(const float4*)(X + base + tid * 4);
    float4 r = *(const float4*)(R + base + tid * 4);
    float v0 = a.x + r.x, v1 = a.y + r.y, v2 = a.z + r.z, v3 = a.w + r.w;

    float s = v0 + v1 + v2 + v3;
#pragma unroll
    for (int o = 16; o > 0; o >>= 1) s += __shfl_xor_sync(0xffffffffu, s, o);
    if ((tid & 31) == 0) red1[tid >> 5] = s;
    __syncthreads();
    if (tid == 0) {
        float tt = 0.f;
#pragma unroll
        for (int i = 0; i < 8; i++) tt += red1[i];
        s_mean = tt * (1.0f / ND);
    }
    __syncthreads();
    const float mean = s_mean;
    float d0 = v0 - mean, d1 = v1 - mean, d2 = v2 - mean, d3 = v3 - mean;
    float q = d0 * d0 + d1 * d1 + d2 * d2 + d3 * d3;
#pragma unroll
    for (int o = 16; o > 0; o >>= 1) q += __shfl_xor_sync(0xffffffffu, q, o);
    if ((tid & 31) == 0) red2[tid >> 5] = q;
    __syncthreads();
    if (tid == 0) {
        float tt = 0.f;
#pragma unroll
        for (int i = 0; i < 8; i++) tt += red2[i];
        s_rstd = rsqrtf(tt * (1.0f / ND) + 1e-5f);
    }
    __syncthreads();
    const float rstd = s_rstd;

    float4 g4 = *(const float4*)(ga + tid * 4);
    float4 b4 = *(const float4*)(be + tid * 4);
    float4 o4;
    o4.x = d0 * rstd * g4.x + b4.x;
    o4.y = d1 * rstd * g4.y + b4.y;
    o4.z = d2 * rstd * g4.z + b4.z;
    o4.w = d3 * rstd * g4.w + b4.w;
    *(float4*)(O + base + tid * 4) = o4;
    uint2 hh; hh.x = h2pack(o4.x, o4.y); hh.y = h2pack(o4.z, o4.w);
    *(uint2*)(O16 + base + tid * 4) = hh;
}

// ---------------- launcher ---------------------------------------------------
extern "C" void kernel_launch(void* const* d_in, const int* in_sizes, int n_in,
                              void* d_out, int out_size) {
    (void)in_sizes; (void)n_in; (void)out_size;
    const float* x    = (const float*)d_in[0];
    const int*   mask = (const int*)  d_in[1];
    const float* wq   = (const float*)d_in[2];
    const float* bq   = (const float*)d_in[3];
    const float* wk   = (const float*)d_in[4];
    const float* bk   = (const float*)d_in[5];
    const float* wv   = (const float*)d_in[6];
    const float* bv   = (const float*)d_in[7];
    const float* wo   = (const float*)d_in[8];
    const float* bo   = (const float*)d_in[9];
    const float* w1   = (const float*)d_in[10];
    const float* b1   = (const float*)d_in[11];
    const float* w2   = (const float*)d_in[12];
    const float* b2   = (const float*)d_in[13];
    const float* l1g  = (const float*)d_in[14];
    const float* l1b  = (const float*)d_in[15];
    const float* l2g  = (const float*)d_in[16];
    const float* l2b  = (const float*)d_in[17];

    float *px, *pt1;
    __half *px16, *pq, *pk, *pv, *pao, *ph, *pwtd, *pwtq;
    cudaGetSymbolAddress((void**)&px,   g_x);
    cudaGetSymbolAddress((void**)&pt1,  g_t1);
    cudaGetSymbolAddress((void**)&px16, g_x16);
    cudaGetSymbolAddress((void**)&pq,   g_q);
    cudaGetSymbolAddress((void**)&pk,   g_k);
    cudaGetSymbolAddress((void**)&pv,   g_v);
    cudaGetSymbolAddress((void**)&pao,  g_ao);
    cudaGetSymbolAddress((void**)&ph,   g_h);
    cudaGetSymbolAddress((void**)&pwtd, g_wtd);
    cudaGetSymbolAddress((void**)&pwtq, g_wtq);

    cudaFuncSetAttribute(gemm_v4, cudaFuncAttributeMaxDynamicSharedMemorySize, GEMM_SMEM_BYTES);
    cudaFuncSetAttribute(attn_f16, cudaFuncAttributeMaxDynamicSharedMemorySize, ATTN_SMEM_BYTES);

    tr_dense<<<dim3(32, 32, 12), dim3(32, 8)>>>(wo, w1, w2, pwtd);
    tr_qkv  <<<dim3(4,  32, 96), dim3(32, 8)>>>(wq, wk, wv, pwtq);

    copy_in<<<(NM * ND / 4) / 256, 256>>>((const float4*)x, (float4*)px, (uint2*)px16);

    const dim3 ggrid(ND / 128, NM / 128);       // (8, 64)
    const dim3 gqkv (ND / 128, NM / 128, 3);

    for (int l = 0; l < NL; l++) {
        const size_t vof = (size_t)l * ND;
        const size_t qb  = (size_t)l * NH * NK;

        gemm_v4<<<gqkv, 128, GEMM_SMEM_BYTES>>>(
            px16, pwtq + (size_t)l * 3 * ND * ND,
            bq + qb, bk + qb, bv + qb,
            (float*)0, pq, pk, pv, 2);

        attn_f16<<<dim3(NS / 128, NB * NH), 256, ATTN_SMEM_BYTES>>>(
            pq, pk, pv, mask, pao);

        gemm_v4<<<ggrid, 128, GEMM_SMEM_BYTES>>>(
            pao, pwtd + (size_t)(l * 3 + 0) * ND * ND,
            bo + vof, (float*)0, (float*)0, pt1, (__half*)0, (__half*)0, (__half*)0, 0);
        add_ln_kernel<<<NM, 256>>>(px, pt1, l1g + vof, l1b + vof, px, px16);

        gemm_v4<<<ggrid, 128, GEMM_SMEM_BYTES>>>(
            px16, pwtd + (size_t)(l * 3 + 1) * ND * ND,
            b1 + vof, (float*)0, (float*)0, (float*)0, ph, (__half*)0, (__half*)0, 1);
        gemm_v4<<<ggrid, 128, GEMM_SMEM_BYTES>>>(
            ph, pwtd + (size_t)(l * 3 + 2) * ND * ND,
            b2 + vof, (float*)0, (float*)0, pt1, (__half*)0, (__half*)0, (__half*)0, 0);

        float* dst = (l == NL - 1) ? (float*)d_out : px;
        add_ln_kernel<<<NM, 256>>>(px, pt1, l2g + vof, l2b + vof, dst, px16);
    }
}

// round 8
// speedup vs baseline: 1.2422x; 1.1319x over previous
#include <cuda_runtime.h>
#include <cuda_fp16.h>
#include <math.h>
#include <stdint.h>

#define NB 4
#define NS 2048
#define ND 1024
#define NH 8
#define NK 128
#define NL 4
#define NM (NB*NS)

// ---------------- scratch ----------------------------------------------------
__device__ float  g_x  [NM*ND];
__device__ float  g_t1 [NM*ND];
__device__ __half g_x16[NM*ND];
__device__ __half g_q  [NM*ND];
__device__ __half g_k  [NM*ND];
__device__ __half g_v  [NM*ND];
__device__ __half g_ao [NM*ND];
__device__ __half g_h  [NM*ND];
__device__ __half g_wtd[12*ND*ND];      // dense weights transposed [l][3][N][K] f16
__device__ __half g_wtq[12*ND*ND];      // qkv weights  transposed [l][3][H*128][K] f16

// ---------------- helpers ----------------------------------------------------
__device__ __forceinline__ float gelu_exact(float x) {
    return 0.5f * x * (1.0f + erff(x * 0.7071067811865476f));
}
__device__ __forceinline__ unsigned sptr(const void* p) {
    return (unsigned)__cvta_generic_to_shared(p);
}
__device__ __forceinline__ unsigned h2pack(float x, float y) {
    __half2 h = __floats2half2_rn(x, y);
    return *(unsigned*)&h;
}
__device__ __forceinline__ void ldsm4(unsigned r[4], unsigned a) {
    asm volatile("ldmatrix.sync.aligned.m8n8.x4.shared.b16 {%0,%1,%2,%3}, [%4];\n"
        : "=r"(r[0]), "=r"(r[1]), "=r"(r[2]), "=r"(r[3]) : "r"(a));
}
__device__ __forceinline__ void ldsm4t(unsigned r[4], unsigned a) {
    asm volatile("ldmatrix.sync.aligned.m8n8.x4.trans.shared.b16 {%0,%1,%2,%3}, [%4];\n"
        : "=r"(r[0]), "=r"(r[1]), "=r"(r[2]), "=r"(r[3]) : "r"(a));
}
__device__ __forceinline__ void mma16816(float c[4], const unsigned a[4],
                                         unsigned b0, unsigned b1) {
    asm volatile("mma.sync.aligned.m16n8k16.row.col.f32.f16.f16.f32 "
        "{%0,%1,%2,%3}, {%4,%5,%6,%7}, {%8,%9}, {%0,%1,%2,%3};\n"
        : "+f"(c[0]), "+f"(c[1]), "+f"(c[2]), "+f"(c[3])
        : "r"(a[0]), "r"(a[1]), "r"(a[2]), "r"(a[3]), "r"(b0), "r"(b1));
}
#define CP16(dst, src) \
    asm volatile("cp.async.cg.shared.global [%0], [%1], 16;" :: "r"(dst), "l"(src) : "memory")
#define CP_COMMIT() asm volatile("cp.async.commit_group;" ::: "memory")

__global__ void copy_in(const float4* __restrict__ s, float4* __restrict__ dx,
                        uint2* __restrict__ dh) {
    int i = blockIdx.x * blockDim.x + threadIdx.x;
    float4 v = s[i];
    dx[i] = v;
    uint2 hh; hh.x = h2pack(v.x, v.y); hh.y = h2pack(v.z, v.w);
    dh[i] = hh;
}

// ---------------- weight transposes (f32 [K][N] -> f16 [N][K]) --------------
__global__ void tr_dense(const float* __restrict__ wo, const float* __restrict__ w1,
                         const float* __restrict__ w2, __half* __restrict__ dst) {
    __shared__ float tile[32][33];
    int z = blockIdx.z, l = z / 3, which = z % 3;
    const float* W = (which == 0 ? wo : which == 1 ? w1 : w2) + (size_t)l * ND * ND;
    __half* D = dst + (size_t)z * ND * ND;
    int n0 = blockIdx.x * 32, k0 = blockIdx.y * 32;
    int tx = threadIdx.x, ty = threadIdx.y;
#pragma unroll
    for (int i = 0; i < 32; i += 8)
        tile[ty + i][tx] = W[(size_t)(k0 + ty + i) * ND + n0 + tx];
    __syncthreads();
#pragma unroll
    for (int i = 0; i < 32; i += 8)
        D[(size_t)(n0 + ty + i) * ND + k0 + tx] = __float2half_rn(tile[tx][ty + i]);
}

__global__ void tr_qkv(const float* __restrict__ wq, const float* __restrict__ wk,
                       const float* __restrict__ wv, __half* __restrict__ dst) {
    __shared__ float tile[32][33];
    int z = blockIdx.z;                 // (l*3+sel)*8 + h
    int l = z / 24, rem = z % 24, sel = rem / 8, h = rem % 8;
    const float* W = (sel == 0 ? wq : sel == 1 ? wk : wv) + (size_t)(l * NH + h) * ND * NK;
    __half* D = dst + (size_t)((l * 3 + sel) * 8 + h) * NK * ND;
    int n0 = blockIdx.x * 32, k0 = blockIdx.y * 32;
    int tx = threadIdx.x, ty = threadIdx.y;
#pragma unroll
    for (int i = 0; i < 32; i += 8)
        tile[ty + i][tx] = W[(size_t)(k0 + ty + i) * NK + n0 + tx];
    __syncthreads();
#pragma unroll
    for (int i = 0; i < 32; i += 8)
        D[(size_t)(n0 + ty + i) * ND + k0 + tx] = __float2half_rn(tile[tx][ty + i]);
}

// ============================================================================
// GEMM v4 (R7-proven): block 128x128, 4 warps, warp 64x64, K-chunk 32,
// 3-stage cp.async pipeline, XOR-swizzled 64B rows.
// ============================================================================
#define BK 32
#define STG 3
#define ASZ (128*BK)
#define NCH (ND/BK)
#define GEMM_SMEM_BYTES (STG*2*ASZ*2)

__global__ __launch_bounds__(128, 2) void gemm_v4(
    const __half* __restrict__ A, const __half* __restrict__ BtBase,
    const float* __restrict__ bias0, const float* __restrict__ bias1,
    const float* __restrict__ bias2,
    float* __restrict__ Cf, __half* __restrict__ Ch0,
    __half* __restrict__ Ch1, __half* __restrict__ Ch2, int mode)
{
    extern __shared__ __half smh[];
    __half* sA = smh;
    __half* sB = smh + STG * ASZ;

    const int tid = threadIdx.x, lane = tid & 31, wid = tid >> 5;
    const int wm = wid >> 1, wn = wid & 1, g = lane >> 2, t = lane & 3;
    const int m0 = blockIdx.y * 128, n0 = blockIdx.x * 128;

    const int sel = blockIdx.z;
    const __half* Bt = BtBase + (size_t)sel * ND * ND;
    const float* bias = (sel == 0) ? bias0 : (sel == 1) ? bias1 : bias2;
    __half* Ch = (sel == 0) ? Ch0 : (sel == 1) ? Ch1 : Ch2;

    float c[4][8][4];
#pragma unroll
    for (int mt = 0; mt < 4; mt++)
#pragma unroll
        for (int nt = 0; nt < 8; nt++)
#pragma unroll
            for (int i = 0; i < 4; i++) c[mt][nt][i] = 0.f;

    const int lr = tid >> 2;
    const int lu = tid & 3;
    const unsigned sA0 = sptr(sA), sB0 = sptr(sB);

    const int arow = wm * 64 + (lane & 15);
    const int axor = (arow >> 1) & 3;
    const int ahi  = lane >> 4;
    const int brow = (lane >> 4) * 8 + (lane & 7);
    const int bxor = (brow >> 1) & 3;
    const int bhi  = (lane >> 3) & 1;

#define LOAD_CHUNK(ck, st) do {                                               \
    int _k0 = (ck) * BK;                                                      \
    _Pragma("unroll")                                                         \
    for (int _i = 0; _i < 4; _i++) {                                          \
        int _r = lr + _i * 32;                                                \
        unsigned _sw = ((unsigned)(lu ^ ((_r >> 1) & 3))) * 16;               \
        CP16(sA0 + (st) * ASZ * 2 + _r * 64 + _sw,                            \
             A + (size_t)(m0 + _r) * ND + _k0 + lu * 8);                      \
        CP16(sB0 + (st) * ASZ * 2 + _r * 64 + _sw,                            \
             Bt + (size_t)(n0 + _r) * ND + _k0 + lu * 8);                     \
    }                                                                         \
    CP_COMMIT();                                                              \
} while (0)

    LOAD_CHUNK(0, 0);
    LOAD_CHUNK(1, 1);

    int st = 0;
    for (int ck = 0; ck < NCH; ck++) {
        if (ck + 2 < NCH) {
            asm volatile("cp.async.wait_group 1;" ::: "memory");
        } else {
            asm volatile("cp.async.wait_group 0;" ::: "memory");
        }
        __syncthreads();
        if (ck + 2 < NCH) {
            int st2 = st + 2; if (st2 >= STG) st2 -= STG;
            LOAD_CHUNK(ck + 2, st2);
        }

        unsigned abuf = sA0 + st * ASZ * 2;
        unsigned bbuf = sB0 + st * ASZ * 2;
#pragma unroll
        for (int ks = 0; ks < 2; ks++) {
            unsigned akoff = ((unsigned)((ks * 2 + ahi) ^ axor)) * 16;
            unsigned a[4][4];
#pragma unroll
            for (int mt = 0; mt < 4; mt++)
                ldsm4(a[mt], abuf + (arow + mt * 16) * 64 + akoff);
            unsigned bkoff = ((unsigned)((ks * 2 + bhi) ^ bxor)) * 16;
#pragma unroll
            for (int p = 0; p < 4; p++) {
                unsigned bf[4];
                ldsm4(bf, bbuf + (brow + wn * 64 + p * 16) * 64 + bkoff);
#pragma unroll
                for (int mt = 0; mt < 4; mt++) {
                    mma16816(c[mt][2 * p],     a[mt], bf[0], bf[1]);
                    mma16816(c[mt][2 * p + 1], a[mt], bf[2], bf[3]);
                }
            }
        }
        if (++st >= STG) st -= STG;
    }

#pragma unroll
    for (int mt = 0; mt < 4; mt++) {
        int r0 = m0 + wm * 64 + mt * 16 + g;
#pragma unroll
        for (int nt = 0; nt < 8; nt++) {
            int col = n0 + wn * 64 + nt * 8 + 2 * t;
            float b0 = bias[col], b1 = bias[col + 1];
            float v0 = c[mt][nt][0] + b0, v1 = c[mt][nt][1] + b1;
            float v2 = c[mt][nt][2] + b0, v3 = c[mt][nt][3] + b1;
            if (mode == 0) {
                *(float2*)(Cf + (size_t)r0 * ND + col)       = make_float2(v0, v1);
                *(float2*)(Cf + (size_t)(r0 + 8) * ND + col) = make_float2(v2, v3);
            } else if (mode == 1) {
                v0 = gelu_exact(v0); v1 = gelu_exact(v1);
                v2 = gelu_exact(v2); v3 = gelu_exact(v3);
                *(unsigned*)(Ch + (size_t)r0 * ND + col)       = h2pack(v0, v1);
                *(unsigned*)(Ch + (size_t)(r0 + 8) * ND + col) = h2pack(v2, v3);
            } else {
                int head = col >> 7, within = col & 127;
                int bb0 = r0 >> 11, s0 = r0 & (NS - 1);
                __half* d0 = Ch + ((size_t)(bb0 * NH + head) * NS + s0) * NK + within;
                *(unsigned*)(d0)          = h2pack(v0, v1);
                *(unsigned*)(d0 + 8 * NK) = h2pack(v2, v3);
            }
        }
    }
}

// ============================================================================
// Flash attention fp16, cp.async-pipelined K/V. BQ=128, BT=64, 256 threads.
// K single-buffered (refilled after rmax barrier), V double-buffered.
// 3 barriers per tile.
// ============================================================================
#define QS_STR 136
#define KS_STR 136
#define VS_STR 136
#define PS_STR 72
#define OFF_Q 0
#define OFF_K (128*QS_STR)                 // 17408
#define OFF_V (OFF_K + 64*KS_STR)          // 26112 ([2][64][136])
#define OFF_P (OFF_V + 2*64*VS_STR)        // 43520
#define HALF_END (OFF_P + 128*PS_STR)      // 52736
#define SOFF_M    0
#define SOFF_L    128
#define SOFF_RMAX 256
#define SOFF_RSUM 512
#define ATTN_SMEM_BYTES (HALF_END*2 + 768*4)

__global__ __launch_bounds__(256) void attn_f16(
    const __half* __restrict__ Qg, const __half* __restrict__ Kg,
    const __half* __restrict__ Vg, const int* __restrict__ Mg,
    __half* __restrict__ Og)
{
    extern __shared__ __half smh[];
    float* smf = (float*)((char*)smh + HALF_END * 2);

    const int tid = threadIdx.x, lane = tid & 31, w = tid >> 5;
    const int wm = w >> 1, wn = w & 1, g = lane >> 2, t = lane & 3;
    const int bh = blockIdx.y, b = bh >> 3, h = bh & 7;
    const int q0 = blockIdx.x * 128;
    const unsigned smb = sptr(smh);

    // K/V tile prefetch via cp.async: 64 rows x 128 halfs each
#define ATTN_LOAD_KV(tnext, vbuf) do {                                        \
    const __half* _Kb = Kg + ((size_t)bh * NS + (tnext)) * NK;                \
    const __half* _Vb = Vg + ((size_t)bh * NS + (tnext)) * NK;                \
    _Pragma("unroll")                                                         \
    for (int _i = 0; _i < 4; _i++) {                                          \
        int _u = tid + _i * 256;                                              \
        int _r = _u >> 4, _c = (_u & 15) * 8;                                 \
        CP16(smb + (OFF_K + _r * KS_STR + _c) * 2, _Kb + _r * NK + _c);       \
        CP16(smb + (OFF_V + (vbuf) * 64 * VS_STR + _r * VS_STR + _c) * 2,     \
             _Vb + _r * NK + _c);                                             \
    }                                                                         \
    CP_COMMIT();                                                              \
} while (0)

    // load Q tile [128 x 128]
    const __half* Qb = Qg + ((size_t)bh * NS + q0) * NK;
#pragma unroll
    for (int i = 0; i < 8; i++) {
        int idx = tid + i * 256;
        int r = idx >> 4, c8 = (idx & 15) * 8;
        *(uint4*)&smh[OFF_Q + r * QS_STR + c8] = *(const uint4*)(Qb + (size_t)r * NK + c8);
    }
    if (tid < 128) { smf[SOFF_M + tid] = -INFINITY; smf[SOFF_L + tid] = 0.f; }

    ATTN_LOAD_KV(0, 0);

    float accz[2][8][4];
#pragma unroll
    for (int mt = 0; mt < 2; mt++)
#pragma unroll
        for (int nt = 0; nt < 8; nt++)
#pragma unroll
            for (int i = 0; i < 4; i++) accz[mt][nt][i] = 0.f;

    const float scale = 0.08838834764831845f;

    for (int tix = 0; tix < NS / 64; tix++) {
        const int t0 = tix * 64;
        const int vb = tix & 1;

        asm volatile("cp.async.wait_group 0;" ::: "memory");
        __syncthreads();                               // K(t), V(t) ready

        // ---- S = Q K^T (128x64), warp tile 32x32
        float sc[2][4][4];
#pragma unroll
        for (int mt = 0; mt < 2; mt++)
#pragma unroll
            for (int nt = 0; nt < 4; nt++)
#pragma unroll
                for (int i = 0; i < 4; i++) sc[mt][nt][i] = 0.f;

        {
            unsigned qbase = smb +
                ((OFF_Q + (wm * 32 + (lane & 15)) * QS_STR + (lane >> 4) * 8)) * 2;
            unsigned kbase = smb +
                ((OFF_K + ((lane >> 4) * 8 + (lane & 7)) * KS_STR + ((lane >> 3) & 1) * 8)) * 2;
#pragma unroll
            for (int ks = 0; ks < 8; ks++) {
                unsigned a0[4], a1[4];
                ldsm4(a0, qbase + ks * 32);
                ldsm4(a1, qbase + 16 * QS_STR * 2 + ks * 32);
                unsigned kb[2][4];
#pragma unroll
                for (int p = 0; p < 2; p++)
                    ldsm4(kb[p], kbase + (wn * 32 + p * 16) * KS_STR * 2 + ks * 32);
#pragma unroll
                for (int p = 0; p < 2; p++) {
                    mma16816(sc[0][2 * p],     a0, kb[p][0], kb[p][1]);
                    mma16816(sc[0][2 * p + 1], a0, kb[p][2], kb[p][3]);
                    mma16816(sc[1][2 * p],     a1, kb[p][0], kb[p][1]);
                    mma16816(sc[1][2 * p + 1], a1, kb[p][2], kb[p][3]);
                }
            }
        }

        // ---- mask + scale, row max
        float rmax[2][2] = {{-INFINITY, -INFINITY}, {-INFINITY, -INFINITY}};
        const size_t mbase = (size_t)b * NS * NS + (size_t)q0 * NS + t0;
#pragma unroll
        for (int mt = 0; mt < 2; mt++) {
            int rl = wm * 32 + mt * 16 + g;
#pragma unroll
            for (int nt = 0; nt < 4; nt++) {
                int cl = wn * 32 + nt * 8 + 2 * t;
                const int* mp = Mg + mbase + (size_t)rl * NS + cl;
                int2 mv0 = *(const int2*)mp;
                int2 mv1 = *(const int2*)(mp + 8 * NS);
                float s0 = (mv0.x == 0) ? -1.0e9f : sc[mt][nt][0] * scale;
                float s1 = (mv0.y == 0) ? -1.0e9f : sc[mt][nt][1] * scale;
                float s2 = (mv1.x == 0) ? -1.0e9f : sc[mt][nt][2] * scale;
                float s3 = (mv1.y == 0) ? -1.0e9f : sc[mt][nt][3] * scale;
                sc[mt][nt][0] = s0; sc[mt][nt][1] = s1;
                sc[mt][nt][2] = s2; sc[mt][nt][3] = s3;
                rmax[mt][0] = fmaxf(rmax[mt][0], fmaxf(s0, s1));
                rmax[mt][1] = fmaxf(rmax[mt][1], fmaxf(s2, s3));
            }
        }
#pragma unroll
        for (int mt = 0; mt < 2; mt++)
#pragma unroll
            for (int hh = 0; hh < 2; hh++) {
                float v = rmax[mt][hh];
                v = fmaxf(v, __shfl_xor_sync(0xffffffffu, v, 1));
                v = fmaxf(v, __shfl_xor_sync(0xffffffffu, v, 2));
                rmax[mt][hh] = v;
            }
        if (t == 0) {
#pragma unroll
            for (int mt = 0; mt < 2; mt++)
#pragma unroll
                for (int hh = 0; hh < 2; hh++)
                    smf[SOFF_RMAX + wn * 128 + wm * 32 + mt * 16 + g + 8 * hh] = rmax[mt][hh];
        }
        __syncthreads();                               // all warps done with K(t)

        // prefetch next K/V (K into single buf, V into vb^1)
        if (tix + 1 < NS / 64) ATTN_LOAD_KV(t0 + 64, vb ^ 1);

        // ---- exp + rowsum + P write + accz rescale
        float mold[2][2], mnew[2][2];
#pragma unroll
        for (int mt = 0; mt < 2; mt++)
#pragma unroll
            for (int hh = 0; hh < 2; hh++) {
                int r = wm * 32 + mt * 16 + g + 8 * hh;
                float tm = fmaxf(smf[SOFF_RMAX + r], smf[SOFF_RMAX + 128 + r]);
                mold[mt][hh] = smf[SOFF_M + r];
                mnew[mt][hh] = fmaxf(mold[mt][hh], tm);
            }
        float rsum[2][2] = {{0.f, 0.f}, {0.f, 0.f}};
#pragma unroll
        for (int mt = 0; mt < 2; mt++)
#pragma unroll
            for (int nt = 0; nt < 4; nt++) {
                float e0 = __expf(sc[mt][nt][0] - mnew[mt][0]);
                float e1 = __expf(sc[mt][nt][1] - mnew[mt][0]);
                float e2 = __expf(sc[mt][nt][2] - mnew[mt][1]);
                float e3 = __expf(sc[mt][nt][3] - mnew[mt][1]);
                rsum[mt][0] += e0 + e1;
                rsum[mt][1] += e2 + e3;
                int r0 = wm * 32 + mt * 16 + g;
                int cl = wn * 32 + nt * 8 + 2 * t;
                *(unsigned*)&smh[OFF_P + r0 * PS_STR + cl]       = h2pack(e0, e1);
                *(unsigned*)&smh[OFF_P + (r0 + 8) * PS_STR + cl] = h2pack(e2, e3);
            }
#pragma unroll
        for (int mt = 0; mt < 2; mt++)
#pragma unroll
            for (int hh = 0; hh < 2; hh++) {
                float v = rsum[mt][hh];
                v += __shfl_xor_sync(0xffffffffu, v, 1);
                v += __shfl_xor_sync(0xffffffffu, v, 2);
                rsum[mt][hh] = v;
            }
        if (t == 0) {
#pragma unroll
            for (int mt = 0; mt < 2; mt++)
#pragma unroll
                for (int hh = 0; hh < 2; hh++)
                    smf[SOFF_RSUM + wn * 128 + wm * 32 + mt * 16 + g + 8 * hh] = rsum[mt][hh];
        }
#pragma unroll
        for (int mt = 0; mt < 2; mt++) {
            float c0 = __expf(mold[mt][0] - mnew[mt][0]);
            float c1 = __expf(mold[mt][1] - mnew[mt][1]);
#pragma unroll
            for (int nt = 0; nt < 8; nt++) {
                accz[mt][nt][0] *= c0; accz[mt][nt][1] *= c0;
                accz[mt][nt][2] *= c1; accz[mt][nt][3] *= c1;
            }
        }
        __syncthreads();                               // P + rsum visible

        if (tid < 128) {
            int r = tid;
            float tm = fmaxf(smf[SOFF_RMAX + r], smf[SOFF_RMAX + 128 + r]);
            float mo = smf[SOFF_M + r];
            float mn = fmaxf(mo, tm);
            float corr = __expf(mo - mn);
            smf[SOFF_L + r] = smf[SOFF_L + r] * corr +
                              smf[SOFF_RSUM + r] + smf[SOFF_RSUM + 128 + r];
            smf[SOFF_M + r] = mn;
        }

        // ---- PV: accz += P[128x64] @ V(vb)[64x128]
        {
            unsigned pbase = smb +
                (OFF_P + (wm * 32 + (lane & 15)) * PS_STR + (lane >> 4) * 8) * 2;
            unsigned vbase = smb +
                (OFF_V + vb * 64 * VS_STR + (lane & 15) * VS_STR + wn * 64 + (lane >> 4) * 8) * 2;
#pragma unroll
            for (int ks = 0; ks < 4; ks++) {
                unsigned a0[4], a1[4];
                ldsm4(a0, pbase + ks * 32);
                ldsm4(a1, pbase + 16 * PS_STR * 2 + ks * 32);
                unsigned vf[4][4];
#pragma unroll
                for (int p = 0; p < 4; p++)
                    ldsm4t(vf[p], vbase + ks * 16 * VS_STR * 2 + p * 32);
#pragma unroll
                for (int p = 0; p < 4; p++) {
                    mma16816(accz[0][2 * p],     a0, vf[p][0], vf[p][1]);
                    mma16816(accz[0][2 * p + 1], a0, vf[p][2], vf[p][3]);
                    mma16816(accz[1][2 * p],     a1, vf[p][0], vf[p][1]);
                    mma16816(accz[1][2 * p + 1], a1, vf[p][2], vf[p][3]);
                }
            }
        }
    }

    __syncthreads();
#pragma unroll
    for (int mt = 0; mt < 2; mt++) {
        int r0 = wm * 32 + mt * 16 + g;
        float inv0 = 1.0f / smf[SOFF_L + r0];
        float inv1 = 1.0f / smf[SOFF_L + r0 + 8];
#pragma unroll
        for (int nt = 0; nt < 8; nt++) {
            int col = wn * 64 + nt * 8 + 2 * t;
            __half* d0 = Og + ((size_t)(b * NS + q0 + r0)) * ND + h * NK + col;
            *(unsigned*)(d0)          = h2pack(accz[mt][nt][0] * inv0, accz[mt][nt][1] * inv0);
            *(unsigned*)(d0 + 8 * ND) = h2pack(accz[mt][nt][2] * inv1, accz[mt][nt][3] * inv1);
        }
    }
}

// ---------------- fused residual add + LayerNorm -----------------------------
__global__ __launch_bounds__(256) void add_ln_kernel(
    const float* __restrict__ X, const float* __restrict__ R,
    const float* __restrict__ ga, const float* __restrict__ be,
    float* __restrict__ O, __half* __restrict__ O16)
{
    __shared__ float red1[8];
    __shared__ float red2[8];
    __shared__ float s_mean, s_rstd;
    const int row = blockIdx.x;
    const int tid = threadIdx.x;
    const size_t base = (size_t)row * ND;

    float4 a = *(const float4*)(X + base + tid * 4);
    float4 r = *(const float4*)(R + base + tid * 4);
    float v0 = a.x + r.x, v1 = a.y + r.y, v2 = a.z + r.z, v3 = a.w + r.w;

    float s = v0 + v1 + v2 + v3;
#pragma unroll
    for (int o = 16; o > 0; o >>= 1) s += __shfl_xor_sync(0xffffffffu, s, o);
    if ((tid & 31) == 0) red1[tid >> 5] = s;
    __syncthreads();
    if (tid == 0) {
        float tt = 0.f;
#pragma unroll
        for (int i = 0; i < 8; i++) tt += red1[i];
        s_mean = tt * (1.0f / ND);
    }
    __syncthreads();
    const float mean = s_mean;
    float d0 = v0 - mean, d1 = v1 - mean, d2 = v2 - mean, d3 = v3 - mean;
    float q = d0 * d0 + d1 * d1 + d2 * d2 + d3 * d3;
#pragma unroll
    for (int o = 16; o > 0; o >>= 1) q += __shfl_xor_sync(0xffffffffu, q, o);
    if ((tid & 31) == 0) red2[tid >> 5] = q;
    __syncthreads();
    if (tid == 0) {
        float tt = 0.f;
#pragma unroll
        for (int i = 0; i < 8; i++) tt += red2[i];
        s_rstd = rsqrtf(tt * (1.0f / ND) + 1e-5f);
    }
    __syncthreads();
    const float rstd = s_rstd;

    float4 g4 = *(const float4*)(ga + tid * 4);
    float4 b4 = *(const float4*)(be + tid * 4);
    float4 o4;
    o4.x = d0 * rstd * g4.x + b4.x;
    o4.y = d1 * rstd * g4.y + b4.y;
    o4.z = d2 * rstd * g4.z + b4.z;
    o4.w = d3 * rstd * g4.w + b4.w;
    *(float4*)(O + base + tid * 4) = o4;
    uint2 hh; hh.x = h2pack(o4.x, o4.y); hh.y = h2pack(o4.z, o4.w);
    *(uint2*)(O16 + base + tid * 4) = hh;
}

// ---------------- launcher ---------------------------------------------------
extern "C" void kernel_launch(void* const* d_in, const int* in_sizes, int n_in,
                              void* d_out, int out_size) {
    (void)in_sizes; (void)n_in; (void)out_size;
    const float* x    = (const float*)d_in[0];
    const int*   mask = (const int*)  d_in[1];
    const float* wq   = (const float*)d_in[2];
    const float* bq   = (const float*)d_in[3];
    const float* wk   = (const float*)d_in[4];
    const float* bk   = (const float*)d_in[5];
    const float* wv   = (const float*)d_in[6];
    const float* bv   = (const float*)d_in[7];
    const float* wo   = (const float*)d_in[8];
    const float* bo   = (const float*)d_in[9];
    const float* w1   = (const float*)d_in[10];
    const float* b1   = (const float*)d_in[11];
    const float* w2   = (const float*)d_in[12];
    const float* b2   = (const float*)d_in[13];
    const float* l1g  = (const float*)d_in[14];
    const float* l1b  = (const float*)d_in[15];
    const float* l2g  = (const float*)d_in[16];
    const float* l2b  = (const float*)d_in[17];

    float *px, *pt1;
    __half *px16, *pq, *pk, *pv, *pao, *ph, *pwtd, *pwtq;
    cudaGetSymbolAddress((void**)&px,   g_x);
    cudaGetSymbolAddress((void**)&pt1,  g_t1);
    cudaGetSymbolAddress((void**)&px16, g_x16);
    cudaGetSymbolAddress((void**)&pq,   g_q);
    cudaGetSymbolAddress((void**)&pk,   g_k);
    cudaGetSymbolAddress((void**)&pv,   g_v);
    cudaGetSymbolAddress((void**)&pao,  g_ao);
    cudaGetSymbolAddress((void**)&ph,   g_h);
    cudaGetSymbolAddress((void**)&pwtd, g_wtd);
    cudaGetSymbolAddress((void**)&pwtq, g_wtq);

    cudaFuncSetAttribute(gemm_v4, cudaFuncAttributeMaxDynamicSharedMemorySize, GEMM_SMEM_BYTES);
    cudaFuncSetAttribute(attn_f16, cudaFuncAttributeMaxDynamicSharedMemorySize, ATTN_SMEM_BYTES);

    tr_dense<<<dim3(32, 32, 12), dim3(32, 8)>>>(wo, w1, w2, pwtd);
    tr_qkv  <<<dim3(4,  32, 96), dim3(32, 8)>>>(wq, wk, wv, pwtq);

    copy_in<<<(NM * ND / 4) / 256, 256>>>((const float4*)x, (float4*)px, (uint2*)px16);

    const dim3 ggrid(ND / 128, NM / 128);
    const dim3 gqkv (ND / 128, NM / 128, 3);

    for (int l = 0; l < NL; l++) {
        const size_t vof = (size_t)l * ND;
        const size_t qb  = (size_t)l * NH * NK;

        gemm_v4<<<gqkv, 128, GEMM_SMEM_BYTES>>>(
            px16, pwtq + (size_t)l * 3 * ND * ND,
            bq + qb, bk + qb, bv + qb,
            (float*)0, pq, pk, pv, 2);

        attn_f16<<<dim3(NS / 128, NB * NH), 256, ATTN_SMEM_BYTES>>>(
            pq, pk, pv, mask, pao);

        gemm_v4<<<ggrid, 128, GEMM_SMEM_BYTES>>>(
            pao, pwtd + (size_t)(l * 3 + 0) * ND * ND,
            bo + vof, (float*)0, (float*)0, pt1, (__half*)0, (__half*)0, (__half*)0, 0);
        add_ln_kernel<<<NM, 256>>>(px, pt1, l1g + vof, l1b + vof, px, px16);

        gemm_v4<<<ggrid, 128, GEMM_SMEM_BYTES>>>(
            px16, pwtd + (size_t)(l * 3 + 1) * ND * ND,
            b1 + vof, (float*)0, (float*)0, (float*)0, ph, (__half*)0, (__half*)0, 1);
        gemm_v4<<<ggrid, 128, GEMM_SMEM_BYTES>>>(
            ph, pwtd + (size_t)(l * 3 + 2) * ND * ND,
            b2 + vof, (float*)0, (float*)0, pt1, (__half*)0, (__half*)0, (__half*)0, 0);

        float* dst = (l == NL - 1) ? (float*)d_out : px;
        add_ln_kernel<<<NM, 256>>>(px, pt1, l2g + vof, l2b + vof, dst, px16);
    }
}